// round 2
// baseline (speedup 1.0000x reference)
#include <cuda_runtime.h>
#include <math.h>

#define N_NODES 50000
#define N_EDGES 800000

#define INV_SQRT8  0.35355339059327373f
#define INV_SQRT32 0.17677669529663687f
#define CG_INV3    0.5773502691896258f   // 1/sqrt(3)
#define CG_INV2    0.7071067811865476f   // 1/sqrt(2)
#define MS_SCALE   0.125f                // 1/sqrt(64)
#define MV_SCALE   0.10206207261596575f  // 1/sqrt(96)
#define NSC_SCALE  0.0625f               // 1/sqrt(256)
#define NEIGH_INV  0.25f                 // 1/sqrt(16)

// Scratch (static device memory — no allocation in kernel_launch)
__device__ __align__(16) float g_xs[N_NODES * 32];    // linear_1 scalar out
__device__ __align__(16) float g_xv[N_NODES * 96];    // linear_1 vector out, [N][3][32] comp-major
__device__ __align__(16) float g_aggs[N_NODES * 64];  // scatter target, [N][64]
__device__ __align__(16) float g_aggv[N_NODES * 288]; // scatter target, [N][3][96] comp-major

__device__ __forceinline__ void red_add_v4(float* addr, float a, float b, float c, float d) {
    asm volatile("red.global.add.v4.f32 [%0], {%1, %2, %3, %4};"
                 :: "l"(addr), "f"(a), "f"(b), "f"(c), "f"(d) : "memory");
}

// ---------------------------------------------------------------------------
// Kernel 0: zero the aggregation buffers
// ---------------------------------------------------------------------------
__global__ void zero_kernel() {
    const int stride = gridDim.x * blockDim.x;
    int i = blockIdx.x * blockDim.x + threadIdx.x;
    const float4 z = make_float4(0.f, 0.f, 0.f, 0.f);
    const int tot_s = N_NODES * 64 / 4;
    const int tot_v = N_NODES * 288 / 4;
    for (int k = i; k < tot_s; k += stride) reinterpret_cast<float4*>(g_aggs)[k] = z;
    for (int k = i; k < tot_v; k += stride) reinterpret_cast<float4*>(g_aggv)[k] = z;
}

// ---------------------------------------------------------------------------
// Kernel 1: linear_1 (per-l channel mixing), one warp per node
// ---------------------------------------------------------------------------
__global__ void lin1_kernel(const float* __restrict__ node_s,
                            const float* __restrict__ node_v,
                            const float* __restrict__ W1s,
                            const float* __restrict__ W1v) {
    __shared__ float sW1s[1024];
    __shared__ float sW1v[1024];
    for (int i = threadIdx.x; i < 1024; i += blockDim.x) {
        sW1s[i] = W1s[i];
        sW1v[i] = W1v[i];
    }
    __syncthreads();

    const int warp = (blockIdx.x * blockDim.x + threadIdx.x) >> 5;
    const int lane = threadIdx.x & 31;
    if (warp >= N_NODES) return;
    const int n = warp;

    // scalars: x_s[n,v] = sum_u node_s[n,u] * W1s[u,v] / sqrt(32)
    float sl = node_s[n * 32 + lane];
    float acc = 0.f;
#pragma unroll
    for (int u = 0; u < 32; u++)
        acc += __shfl_sync(0xffffffffu, sl, u) * sW1s[u * 32 + lane];
    g_xs[n * 32 + lane] = acc * INV_SQRT32;

    // vectors, per component c
#pragma unroll
    for (int c = 0; c < 3; c++) {
        float vl = node_v[n * 96 + lane * 3 + c];
        float a = 0.f;
#pragma unroll
        for (int u = 0; u < 32; u++)
            a += __shfl_sync(0xffffffffu, vl, u) * sW1v[u * 32 + lane];
        g_xv[n * 96 + c * 32 + lane] = a * INV_SQRT32;
    }
}

// ---------------------------------------------------------------------------
// Kernel 2: per-edge radial MLP + CG tensor product + scatter via red.v4
// 8 threads per edge; thread `sub` owns channels [4*sub, 4*sub+3]
// ---------------------------------------------------------------------------
__global__ void edge_kernel(const float* __restrict__ emb,
                            const float* __restrict__ sh0,
                            const float* __restrict__ sh1,
                            const int*   __restrict__ src,
                            const int*   __restrict__ dst,
                            const float* __restrict__ Wm1,
                            const float* __restrict__ Wm2) {
    __shared__ float sWm1[64];
    __shared__ float sWm2[1280];
    for (int i = threadIdx.x; i < 64; i += blockDim.x) sWm1[i] = Wm1[i];
    for (int i = threadIdx.x; i < 1280; i += blockDim.x) sWm2[i] = Wm2[i];
    __syncthreads();

    const int t = blockIdx.x * blockDim.x + threadIdx.x;
    const int e = t >> 3;
    if (e >= N_EDGES) return;
    const int sub = t & 7;
    const int u0 = sub * 4;

    // ---- radial MLP: h = silu(emb @ Wm1 / sqrt8); w = h @ Wm2 / sqrt8 ----
    float embv = emb[e * 8 + sub];
    float hacc = 0.f;
#pragma unroll
    for (int k = 0; k < 8; k++) {
        float ek = __shfl_sync(0xffffffffu, embv, k, 8);
        hacc += ek * sWm1[k * 8 + sub];
    }
    hacc *= INV_SQRT8;
    float h = hacc / (1.f + expf(-hacc));   // silu

    float w[5][4];
#pragma unroll
    for (int p = 0; p < 5; p++)
#pragma unroll
        for (int j = 0; j < 4; j++) w[p][j] = 0.f;

#pragma unroll
    for (int k = 0; k < 8; k++) {
        float hk = __shfl_sync(0xffffffffu, h, k, 8);
        const float* wrow = &sWm2[k * 160 + u0];
#pragma unroll
        for (int p = 0; p < 5; p++)
#pragma unroll
            for (int j = 0; j < 4; j++)
                w[p][j] += hk * wrow[p * 32 + j];
    }
    const float wscale = INV_SQRT8 * NEIGH_INV;  // fold 1/sqrt(HID) and 1/sqrt(avg_neigh)
#pragma unroll
    for (int p = 0; p < 5; p++)
#pragma unroll
        for (int j = 0; j < 4; j++) w[p][j] *= wscale;

    // ---- gather source features (L2-resident scratch) ----
    const int ns = __ldg(&src[e]);
    const int nd = __ldg(&dst[e]);
    const float q0  = __ldg(&sh0[e]);
    const float s1x = __ldg(&sh1[e * 3 + 0]);
    const float s1y = __ldg(&sh1[e * 3 + 1]);
    const float s1z = __ldg(&sh1[e * 3 + 2]);

    const float4 S  = *reinterpret_cast<const float4*>(g_xs + ns * 32 + u0);
    const float4 VX = *reinterpret_cast<const float4*>(g_xv + ns * 96 + u0);
    const float4 VY = *reinterpret_cast<const float4*>(g_xv + ns * 96 + 32 + u0);
    const float4 VZ = *reinterpret_cast<const float4*>(g_xv + ns * 96 + 64 + u0);
    const float s_[4] = {S.x, S.y, S.z, S.w};
    const float vx[4] = {VX.x, VX.y, VX.z, VX.w};
    const float vy[4] = {VY.x, VY.y, VY.z, VY.w};
    const float vz[4] = {VZ.x, VZ.y, VZ.z, VZ.w};

    float P1[4], P2[4], P3[3][4], P4[3][4], P5[3][4];
#pragma unroll
    for (int j = 0; j < 4; j++) {
        const float dot = vx[j] * s1x + vy[j] * s1y + vz[j] * s1z;
        const float cx = vy[j] * s1z - vz[j] * s1y;
        const float cy = vz[j] * s1x - vx[j] * s1z;
        const float cz = vx[j] * s1y - vy[j] * s1x;
        P1[j]    = w[0][j] * s_[j] * q0;
        P2[j]    = w[1][j] * dot * CG_INV3;
        P3[0][j] = w[2][j] * s_[j] * s1x;
        P3[1][j] = w[2][j] * s_[j] * s1y;
        P3[2][j] = w[2][j] * s_[j] * s1z;
        P4[0][j] = w[3][j] * vx[j] * q0;
        P4[1][j] = w[3][j] * vy[j] * q0;
        P4[2][j] = w[3][j] * vz[j] * q0;
        P5[0][j] = w[4][j] * cx * CG_INV2;
        P5[1][j] = w[4][j] * cy * CG_INV2;
        P5[2][j] = w[4][j] * cz * CG_INV2;
    }

    // ---- scatter: 11 vector reductions per thread (88 per edge) ----
    float* as_base = g_aggs + nd * 64 + u0;
    red_add_v4(as_base,      P1[0], P1[1], P1[2], P1[3]);
    red_add_v4(as_base + 32, P2[0], P2[1], P2[2], P2[3]);
#pragma unroll
    for (int c = 0; c < 3; c++) {
        float* av_base = g_aggv + nd * 288 + c * 96 + u0;
        red_add_v4(av_base,      P3[c][0], P3[c][1], P3[c][2], P3[c][3]);
        red_add_v4(av_base + 32, P4[c][0], P4[c][1], P4[c][2], P4[c][3]);
        red_add_v4(av_base + 64, P5[c][0], P5[c][1], P5[c][2], P5[c][3]);
    }
}

// ---------------------------------------------------------------------------
// Kernel 3: linear_2 + self-connection TP + output, one warp per node
// ---------------------------------------------------------------------------
__global__ void node_out_kernel(const float* __restrict__ node_s,
                                const float* __restrict__ node_v,
                                const float* __restrict__ attrs,
                                const float* __restrict__ W2s,
                                const float* __restrict__ W2v,
                                const float* __restrict__ Wscs,
                                const float* __restrict__ Wscv,
                                float* __restrict__ out) {
    extern __shared__ float dyn[];
    float* sWscs = dyn;          // 8192 floats
    float* sWscv = dyn + 8192;   // 8192 floats
    __shared__ float sW2s[2048];
    __shared__ float sW2v[3072];
    for (int i = threadIdx.x; i < 8192; i += blockDim.x) {
        sWscs[i] = Wscs[i];
        sWscv[i] = Wscv[i];
    }
    for (int i = threadIdx.x; i < 2048; i += blockDim.x) sW2s[i] = W2s[i];
    for (int i = threadIdx.x; i < 3072; i += blockDim.x) sW2v[i] = W2v[i];
    __syncthreads();

    const int warp = (blockIdx.x * blockDim.x + threadIdx.x) >> 5;
    const int lane = threadIdx.x & 31;
    if (warp >= N_NODES) return;
    const int n = warp;

    // m_s = agg_s @ W2_s / sqrt(64)
    float a0 = g_aggs[n * 64 + lane];
    float a1 = g_aggs[n * 64 + 32 + lane];
    float ms = 0.f;
#pragma unroll
    for (int k = 0; k < 32; k++)
        ms += __shfl_sync(0xffffffffu, a0, k) * sW2s[k * 32 + lane];
#pragma unroll
    for (int k = 0; k < 32; k++)
        ms += __shfl_sync(0xffffffffu, a1, k) * sW2s[(32 + k) * 32 + lane];
    ms *= MS_SCALE;

    // m_v[c] = agg_v[:,c] @ W2_v / sqrt(96)
    float mv[3];
#pragma unroll
    for (int c = 0; c < 3; c++) {
        float g0 = g_aggv[n * 288 + c * 96 + lane];
        float g1 = g_aggv[n * 288 + c * 96 + 32 + lane];
        float g2 = g_aggv[n * 288 + c * 96 + 64 + lane];
        float acc = 0.f;
#pragma unroll
        for (int k = 0; k < 32; k++)
            acc += __shfl_sync(0xffffffffu, g0, k) * sW2v[k * 32 + lane];
#pragma unroll
        for (int k = 0; k < 32; k++)
            acc += __shfl_sync(0xffffffffu, g1, k) * sW2v[(32 + k) * 32 + lane];
#pragma unroll
        for (int k = 0; k < 32; k++)
            acc += __shfl_sync(0xffffffffu, g2, k) * sW2v[(64 + k) * 32 + lane];
        mv[c] = acc * MV_SCALE;
    }

    // self connection: sc[v] = sum_{u,a} feat_u * attr_a * Wsc[u,a,v] / 16
    float areg = (lane < 8) ? attrs[n * 8 + lane] : 0.f;
    float at[8];
#pragma unroll
    for (int a = 0; a < 8; a++) at[a] = __shfl_sync(0xffffffffu, areg, a);

    float sl  = node_s[n * 32 + lane];
    float vl0 = node_v[n * 96 + lane * 3 + 0];
    float vl1 = node_v[n * 96 + lane * 3 + 1];
    float vl2 = node_v[n * 96 + lane * 3 + 2];

    float scs = 0.f, scv0 = 0.f, scv1 = 0.f, scv2 = 0.f;
#pragma unroll 8
    for (int u = 0; u < 32; u++) {
        float su  = __shfl_sync(0xffffffffu, sl, u);
        float vu0 = __shfl_sync(0xffffffffu, vl0, u);
        float vu1 = __shfl_sync(0xffffffffu, vl1, u);
        float vu2 = __shfl_sync(0xffffffffu, vl2, u);
        float m_s = 0.f, m_v = 0.f;
        const float* ps = &sWscs[u * 256 + lane];
        const float* pv = &sWscv[u * 256 + lane];
#pragma unroll
        for (int a = 0; a < 8; a++) {
            m_s += at[a] * ps[a * 32];
            m_v += at[a] * pv[a * 32];
        }
        scs  += su  * m_s;
        scv0 += vu0 * m_v;
        scv1 += vu1 * m_v;
        scv2 += vu2 * m_v;
    }

    out[n * 128 + lane] = ms + scs * NSC_SCALE;
    out[n * 128 + 32 + lane * 3 + 0] = mv[0] + scv0 * NSC_SCALE;
    out[n * 128 + 32 + lane * 3 + 1] = mv[1] + scv1 * NSC_SCALE;
    out[n * 128 + 32 + lane * 3 + 2] = mv[2] + scv2 * NSC_SCALE;
}

// ---------------------------------------------------------------------------
extern "C" void kernel_launch(void* const* d_in, const int* in_sizes, int n_in,
                              void* d_out, int out_size) {
    const float* node_s     = (const float*)d_in[0];
    const float* node_v     = (const float*)d_in[1];
    const float* node_attrs = (const float*)d_in[2];
    const float* edge_emb   = (const float*)d_in[3];
    const float* edge_sh0   = (const float*)d_in[4];
    const float* edge_sh1   = (const float*)d_in[5];
    const float* W1_s       = (const float*)d_in[6];
    const float* W1_v       = (const float*)d_in[7];
    const float* Wm1        = (const float*)d_in[8];
    const float* Wm2        = (const float*)d_in[9];
    const float* W2_s       = (const float*)d_in[10];
    const float* W2_v       = (const float*)d_in[11];
    const float* Wsc_s      = (const float*)d_in[12];
    const float* Wsc_v      = (const float*)d_in[13];
    const int*   edge_src   = (const int*)d_in[14];
    const int*   edge_dst   = (const int*)d_in[15];
    float* out = (float*)d_out;

    cudaFuncSetAttribute(node_out_kernel,
                         cudaFuncAttributeMaxDynamicSharedMemorySize, 16384 * sizeof(float));

    zero_kernel<<<2048, 256>>>();
    lin1_kernel<<<(N_NODES + 7) / 8, 256>>>(node_s, node_v, W1_s, W1_v);
    edge_kernel<<<(N_EDGES * 8 + 255) / 256, 256>>>(edge_emb, edge_sh0, edge_sh1,
                                                    edge_src, edge_dst, Wm1, Wm2);
    node_out_kernel<<<(N_NODES + 15) / 16, 512, 16384 * sizeof(float)>>>(
        node_s, node_v, node_attrs, W2_s, W2_v, Wsc_s, Wsc_v, out);
}